// round 5
// baseline (speedup 1.0000x reference)
#include <cuda_runtime.h>
#include <cstdint>

#define S_LEN 2048
#define B_SZ  32
#define I_DIM 256
#define H_DIM 512

#define NCLUSTERS    16
#define CRANKS       8
#define ROWS_PER_CTA 64
#define REC_THREADS  512

#define CHUNK_FLOATS 20                       // 16 data + 4 pad (bank-conflict-free)
#define BUF_BYTES    (32 * CHUNK_FLOATS * 4)  // 2560 B per (batch,parity) th buffer

// ---------------- PTX helpers ----------------
__device__ __forceinline__ uint32_t smem_u32(const void* p) {
    uint32_t a;
    asm("{ .reg .u64 t; cvta.to.shared.u64 t, %1; cvt.u32.u64 %0, t; }" : "=r"(a) : "l"(p));
    return a;
}
__device__ __forceinline__ uint32_t mapa_cluster(uint32_t addr, uint32_t rank) {
    uint32_t r;
    asm("mapa.shared::cluster.u32 %0, %1, %2;" : "=r"(r) : "r"(addr), "r"(rank));
    return r;
}
__device__ __forceinline__ void mbar_init(uint32_t mbar, uint32_t cnt) {
    asm volatile("mbarrier.init.shared.b64 [%0], %1;" :: "r"(mbar), "r"(cnt) : "memory");
}
__device__ __forceinline__ void mbar_expect_tx(uint32_t mbar, uint32_t bytes) {
    asm volatile("mbarrier.arrive.expect_tx.shared.b64 _, [%0], %1;" :: "r"(mbar), "r"(bytes) : "memory");
}
__device__ __forceinline__ void mbar_wait(uint32_t mbar, uint32_t phase) {
    uint32_t done = 0;
    while (!done) {
        asm volatile(
            "{\n\t.reg .pred p;\n\t"
            "mbarrier.try_wait.parity.acquire.cluster.shared::cta.b64 p, [%1], %2, 0x989680;\n\t"
            "selp.b32 %0, 1, 0, p;\n\t}"
            : "=r"(done) : "r"(mbar), "r"(phase) : "memory");
    }
}
__device__ __forceinline__ void st_async_b64(uint32_t daddr, unsigned long long v, uint32_t mbar) {
    asm volatile("st.async.shared::cluster.mbarrier::complete_tx::bytes.b64 [%0], %1, [%2];"
                 :: "r"(daddr), "l"(v), "r"(mbar) : "memory");
}
__device__ __forceinline__ unsigned long long ffma2(unsigned long long a, unsigned long long b,
                                                    unsigned long long c) {
    unsigned long long d;
    asm("fma.rn.f32x2 %0, %1, %2, %3;" : "=l"(d) : "l"(a), "l"(b), "l"(c));
    return d;
}
__device__ __forceinline__ float fold2(unsigned long long v) {
    union { unsigned long long u; float2 f; } c; c.u = v;
    return c.f.x + c.f.y;
}
__device__ __forceinline__ unsigned long long pack2(float x, float y) {
    unsigned long long r;
    asm("mov.b64 %0, {%1, %2};" : "=l"(r) : "r"(__float_as_uint(x)), "r"(__float_as_uint(y)));
    return r;
}
__device__ __forceinline__ float fast_tanh(float h) {
    float hc = fminf(fmaxf(h, -15.f), 15.f);
    float e2 = __expf(2.f * hc);
    return __fdividef(e2 - 1.f, e2 + 1.f);
}
__device__ __forceinline__ void cluster_sync() {
    asm volatile("barrier.cluster.arrive.aligned;\n\tbarrier.cluster.wait.aligned;" ::: "memory");
}

// ---------------- xproj GEMM (f32x2): out[m,n] = sum_k x[m,k] * Wx[n,k] ----------------
#define BM 128
#define BN 128
#define BK 16

__global__ void __launch_bounds__(256, 2)
xproj_kernel(const float* __restrict__ x,
             const float* __restrict__ Wx,
             float* __restrict__ out)
{
    __shared__ float As[BK][BM];
    __shared__ float Bs[BK][BN];
    const int tid = threadIdx.x;
    const int m0 = blockIdx.y * BM;
    const int n0 = blockIdx.x * BN;
    const int tx = tid & 15;
    const int ty = tid >> 4;

    unsigned long long acc[8][4];   // [i][jpair], lo = col 2j, hi = col 2j+1
#pragma unroll
    for (int i = 0; i < 8; i++)
#pragma unroll
        for (int j = 0; j < 4; j++) acc[i][j] = 0ull;

    const float* Aptr = x  + (size_t)m0 * I_DIM;
    const float* Bptr = Wx + (size_t)n0 * I_DIM;

    for (int k0 = 0; k0 < I_DIM; k0 += BK) {
#pragma unroll
        for (int l = 0; l < 2; l++) {
            int idx = tid + l * 256;
            int r   = idx >> 2;
            int c4  = (idx & 3) * 4;
            float4 a = *(const float4*)(Aptr + (size_t)r * I_DIM + k0 + c4);
            As[c4 + 0][r] = a.x; As[c4 + 1][r] = a.y;
            As[c4 + 2][r] = a.z; As[c4 + 3][r] = a.w;
            float4 b = *(const float4*)(Bptr + (size_t)r * I_DIM + k0 + c4);
            Bs[c4 + 0][r] = b.x; Bs[c4 + 1][r] = b.y;
            Bs[c4 + 2][r] = b.z; Bs[c4 + 3][r] = b.w;
        }
        __syncthreads();
#pragma unroll
        for (int kk = 0; kk < BK; kk++) {
            float4 ra0 = *(const float4*)&As[kk][ty * 8];
            float4 ra1 = *(const float4*)&As[kk][ty * 8 + 4];
            float ra[8] = {ra0.x, ra0.y, ra0.z, ra0.w, ra1.x, ra1.y, ra1.z, ra1.w};
            const ulonglong2* rbp = (const ulonglong2*)&Bs[kk][tx * 8];
            ulonglong2 rb01 = rbp[0];
            ulonglong2 rb23 = rbp[1];
#pragma unroll
            for (int i = 0; i < 8; i++) {
                unsigned long long rai = pack2(ra[i], ra[i]);
                acc[i][0] = ffma2(rai, rb01.x, acc[i][0]);
                acc[i][1] = ffma2(rai, rb01.y, acc[i][1]);
                acc[i][2] = ffma2(rai, rb23.x, acc[i][2]);
                acc[i][3] = ffma2(rai, rb23.y, acc[i][3]);
            }
        }
        __syncthreads();
    }

#pragma unroll
    for (int i = 0; i < 8; i++) {
        float* o = out + (size_t)(m0 + ty * 8 + i) * H_DIM + n0 + tx * 8;
        union { unsigned long long u; float2 f; } c0, c1, c2, c3;
        c0.u = acc[i][0]; c1.u = acc[i][1]; c2.u = acc[i][2]; c3.u = acc[i][3];
        *(float4*)o       = make_float4(c0.f.x, c0.f.y, c1.f.x, c1.f.y);
        *(float4*)(o + 4) = make_float4(c2.f.x, c2.f.y, c3.f.x, c3.f.y);
    }
}

// ---------------- recurrence (staggered batches, shfl reduce) ----------------
// 16 clusters x 8 CTAs; cluster c: batches (2c, 2c+1). CTA rank r: rows
// [r*64, r*64+64). Warp w owns rows 4w..4w+3; lane l covers k in [16l,16l+16).
// Each step = 2 phases (batch 0, batch 1). Per phase: mbar wait -> LDS.128 th
// (padded, conflict-free) -> 32 FFMA2 -> 20 shfl.bfly -> lanes 0,1 update 2
// rows each (float2), tanh, pack -> 8x st.async.b64 to peers. 4 th buffers
// [batch][parity], 4 mbars. No __syncthreads in the loop.
struct RecSmem {
    float th[4][32][CHUNK_FLOATS];   // [b*2+p][chunk][slot]  10240 B
    unsigned long long mbar[4];
};

__global__ void __cluster_dims__(CRANKS, 1, 1) __launch_bounds__(REC_THREADS, 1)
rec_kernel(const float* __restrict__ Wh,
           const float* __restrict__ tau,
           const float* __restrict__ bias,
           float* __restrict__ out)
{
    __shared__ __align__(16) RecSmem sm;

    const int cid  = blockIdx.x / CRANKS;
    const int rank = blockIdx.x % CRANKS;
    const int t    = threadIdx.x;
    const int w    = t >> 5;
    const int l    = t & 31;

    // Weights: rows 4w..4w+3, k in [16l, 16l+16), as f32x2 pairs (64 floats)
    unsigned long long wr[4][8];
#pragma unroll
    for (int i = 0; i < 4; i++) {
        const ulonglong2* rp = (const ulonglong2*)
            (Wh + (size_t)(rank * ROWS_PER_CTA + 4 * w + i) * H_DIM + 16 * l);
#pragma unroll
        for (int q = 0; q < 4; q++) {
            ulonglong2 v = rp[q];
            wr[i][2*q]   = v.x;
            wr[i][2*q+1] = v.y;
        }
    }

    const uint32_t th_base   = smem_u32(&sm.th[0][0][0]);
    const uint32_t mbar_base = smem_u32(&sm.mbar[0]);
    const uint32_t mbar_rel  = mbar_base - th_base;

    uint32_t peer_th[CRANKS];
#pragma unroll
    for (int r = 0; r < CRANKS; r++) peer_th[r] = mapa_cluster(th_base, r);

    if (t == 0) {
#pragma unroll
        for (int m = 0; m < 4; m++) {
            mbar_init(mbar_base + m * 8, 1);
            mbar_expect_tx(mbar_base + m * 8, 2048);
        }
    }
    __syncthreads();
    cluster_sync();

    // lanes 0,1: own 2 adjacent rows (lane0: 4w,4w+1; lane1: 4w+2,4w+3)
    const int rl = 4 * w + 2 * l;                 // valid for l<2
    const int hg = rank * ROWS_PER_CTA + rl;
    float* outp0 = out + (size_t)(cid * 2 + 0) * S_LEN * H_DIM + hg;
    float* outp1 = out + (size_t)(cid * 2 + 1) * S_LEN * H_DIM + hg;
    float2 invt2 = make_float2(1.f, 1.f), bias2 = make_float2(0.f, 0.f);
    float2 h0 = make_float2(0.f, 0.f), h1 = make_float2(0.f, 0.f);
    if (l < 2) {
        invt2 = make_float2(1.f / tau[hg], 1.f / tau[hg + 1]);
        bias2 = *(const float2*)(bias + hg);
    }
    // destination byte offset of this lane's row pair within a th buffer
    const uint32_t dstoff = (uint32_t)((hg >> 4) * (CHUNK_FLOATS * 4) + (hg & 15) * 4);

#define SEND_PAIR(BP, PK)                                                      \
    {                                                                          \
        uint32_t _d = (uint32_t)(BP) * BUF_BYTES + dstoff;                     \
        uint32_t _m = mbar_rel + (uint32_t)(BP) * 8u;                          \
        _Pragma("unroll")                                                      \
        for (int _r = 0; _r < CRANKS; _r++)                                    \
            st_async_b64(peer_th[_r] + _d, (PK), peer_th[_r] + _m);            \
    }

    // ---- step 0 (v = 0, no wait): both batches ----
    if (l < 2) {
        float2 xp = *(const float2*)outp0;
        h0.x = (xp.x + bias2.x) * invt2.x;
        h0.y = (xp.y + bias2.y) * invt2.y;
        *(float2*)outp0 = h0;
        SEND_PAIR(0 * 2 + 1, pack2(fast_tanh(h0.x), fast_tanh(h0.y)))
        xp = *(const float2*)outp1;
        h1.x = (xp.x + bias2.x) * invt2.x;
        h1.y = (xp.y + bias2.y) * invt2.y;
        *(float2*)outp1 = h1;
        SEND_PAIR(1 * 2 + 1, pack2(fast_tanh(h1.x), fast_tanh(h1.y)))
    }

    uint32_t ph00 = 0, ph01 = 0, ph10 = 0, ph11 = 0;

#define PHASE(B, P, PH, STEP, LAST)                                            \
    {                                                                          \
        float* _op = (B) ? outp1 : outp0;                                      \
        float2 xp = make_float2(0.f, 0.f);                                     \
        if (l < 2) xp = *(const float2*)(_op + (size_t)(STEP) * H_DIM);        \
        mbar_wait(mbar_base + ((B) * 2 + (P)) * 8, (PH));                      \
        if (t == 0) mbar_expect_tx(mbar_base + ((B) * 2 + (P)) * 8, 2048);     \
        const ulonglong2* tc =                                                 \
            (const ulonglong2*)&sm.th[(B) * 2 + (P)][l][0];                    \
        ulonglong2 c0 = tc[0], c1 = tc[1], c2 = tc[2], c3 = tc[3];             \
        unsigned long long a0 = 0, a1 = 0, a2 = 0, a3 = 0;                     \
        a0 = ffma2(wr[0][0], c0.x, a0); a0 = ffma2(wr[0][1], c0.y, a0);        \
        a0 = ffma2(wr[0][2], c1.x, a0); a0 = ffma2(wr[0][3], c1.y, a0);        \
        a0 = ffma2(wr[0][4], c2.x, a0); a0 = ffma2(wr[0][5], c2.y, a0);        \
        a0 = ffma2(wr[0][6], c3.x, a0); a0 = ffma2(wr[0][7], c3.y, a0);        \
        a1 = ffma2(wr[1][0], c0.x, a1); a1 = ffma2(wr[1][1], c0.y, a1);        \
        a1 = ffma2(wr[1][2], c1.x, a1); a1 = ffma2(wr[1][3], c1.y, a1);        \
        a1 = ffma2(wr[1][4], c2.x, a1); a1 = ffma2(wr[1][5], c2.y, a1);        \
        a1 = ffma2(wr[1][6], c3.x, a1); a1 = ffma2(wr[1][7], c3.y, a1);        \
        a2 = ffma2(wr[2][0], c0.x, a2); a2 = ffma2(wr[2][1], c0.y, a2);        \
        a2 = ffma2(wr[2][2], c1.x, a2); a2 = ffma2(wr[2][3], c1.y, a2);        \
        a2 = ffma2(wr[2][4], c2.x, a2); a2 = ffma2(wr[2][5], c2.y, a2);        \
        a2 = ffma2(wr[2][6], c3.x, a2); a2 = ffma2(wr[2][7], c3.y, a2);        \
        a3 = ffma2(wr[3][0], c0.x, a3); a3 = ffma2(wr[3][1], c0.y, a3);        \
        a3 = ffma2(wr[3][2], c1.x, a3); a3 = ffma2(wr[3][3], c1.y, a3);        \
        a3 = ffma2(wr[3][4], c2.x, a3); a3 = ffma2(wr[3][5], c2.y, a3);        \
        a3 = ffma2(wr[3][6], c3.x, a3); a3 = ffma2(wr[3][7], c3.y, a3);        \
        float s0 = fold2(a0), s1 = fold2(a1), s2 = fold2(a2), s3 = fold2(a3);  \
        _Pragma("unroll")                                                      \
        for (int _o = 16; _o >= 1; _o >>= 1) {                                 \
            s0 += __shfl_xor_sync(0xffffffffu, s0, _o);                        \
            s1 += __shfl_xor_sync(0xffffffffu, s1, _o);                        \
            s2 += __shfl_xor_sync(0xffffffffu, s2, _o);                        \
            s3 += __shfl_xor_sync(0xffffffffu, s3, _o);                        \
        }                                                                      \
        if (l < 2) {                                                           \
            float sa = (l == 0) ? s0 : s2;                                     \
            float sb = (l == 0) ? s1 : s3;                                     \
            float2* hh = (B) ? &h1 : &h0;                                      \
            hh->x += (xp.x - hh->x + sa + bias2.x) * invt2.x;                  \
            hh->y += (xp.y - hh->y + sb + bias2.y) * invt2.y;                  \
            *(float2*)(_op + (size_t)(STEP) * H_DIM) = *hh;                    \
            if (!(LAST))                                                       \
                SEND_PAIR((B) * 2 + ((P) ^ 1),                                 \
                          pack2(fast_tanh(hh->x), fast_tanh(hh->y)))           \
        }                                                                      \
        (PH) ^= 1;                                                             \
    }

    for (int s = 1; s < S_LEN - 1; s += 2) {
        PHASE(0, 1, ph01, s, 0)
        PHASE(1, 1, ph11, s, 0)
        PHASE(0, 0, ph00, s + 1, 0)
        PHASE(1, 0, ph10, s + 1, 0)
    }
    PHASE(0, 1, ph01, S_LEN - 1, 1)
    PHASE(1, 1, ph11, S_LEN - 1, 1)
#undef PHASE
#undef SEND_PAIR

    cluster_sync();   // no CTA exits while peers' st.async may target its smem
}

extern "C" void kernel_launch(void* const* d_in, const int* in_sizes, int n_in,
                              void* d_out, int out_size)
{
    const float* x    = (const float*)d_in[0];
    const float* Wx   = (const float*)d_in[1];
    const float* Wh   = (const float*)d_in[2];
    const float* tau  = (const float*)d_in[3];
    const float* bias = (const float*)d_in[4];
    float* out = (float*)d_out;

    dim3 g1(H_DIM / BN, (B_SZ * S_LEN) / BM);
    xproj_kernel<<<g1, 256>>>(x, Wx, out);

    rec_kernel<<<NCLUSTERS * CRANKS, REC_THREADS>>>(Wh, tau, bias, out);
}